// round 6
// baseline (speedup 1.0000x reference)
#include <cuda_runtime.h>
#include <math.h>
#include <cstdint>

#define BATCH 512
#define NTOK  16
#define CDIM  256
#define KCODE 8192
#define NSTAGE 16
#define BNC (BATCH*NTOK*CDIM)   // 2097152

// ---------------- device globals (scratch) ----------------
__device__ float  g_fres[BNC];
__device__ float  g_fhat[BNC];
__device__ __align__(16) signed char g_ad[3][BNC];        // rest digits d0,d1,d2 (scale 2^20)
__device__ __align__(16) signed char g_bd[3][KCODE*CDIM]; // emb  digits d0,d1,d2 (scale 2^35)
__device__ float  g_t1[BATCH*NTOK];
__device__ float  g_esq[KCODE];
__device__ int    g_idx[BATCH*NTOK];
__device__ float  g_pd[BATCH*NTOK*128];
__device__ int    g_pi[BATCH*NTOK*128];
__device__ double g_m[NSTAGE];

// ---------------- helpers ----------------
#define CP_ASYNC16(dst, src) \
    asm volatile("cp.async.cg.shared.global [%0], [%1], 16;" :: "r"(dst), "l"(src) : "memory")
#define CP_COMMIT() asm volatile("cp.async.commit_group;" ::: "memory")
#define CP_WAIT(n)  asm volatile("cp.async.wait_group %0;" :: "n"(n) : "memory")

__device__ __forceinline__ uint32_t smem_u32(const void* p) {
    uint32_t a;
    asm("{ .reg .u64 t; cvta.to.shared.u64 t, %1; cvt.u32.u64 %0, t; }" : "=r"(a) : "l"(p));
    return a;
}
__device__ __forceinline__ void imma(int* c, const uint32_t* a, const uint32_t* b) {
    asm volatile("mma.sync.aligned.m16n8k32.row.col.s32.s8.s8.s32 "
        "{%0,%1,%2,%3}, {%4,%5,%6,%7}, {%8,%9}, {%0,%1,%2,%3};"
        : "+r"(c[0]), "+r"(c[1]), "+r"(c[2]), "+r"(c[3])
        : "r"(a[0]), "r"(a[1]), "r"(a[2]), "r"(a[3]), "r"(b[0]), "r"(b[1]));
}
__device__ __forceinline__ void digit_split(int R, signed char& d0, signed char& d1, signed char& d2) {
    int x0 = (int)(signed char)(R & 0xFF); R = (R - x0) >> 8;
    int x1 = (int)(signed char)(R & 0xFF); R = (R - x1) >> 8;
    d0 = (signed char)x0; d1 = (signed char)x1; d2 = (signed char)R;
}

// ---------------- init ----------------
__global__ void init_kernel(const float* __restrict__ f) {
    size_t i = (size_t)blockIdx.x * 256 + threadIdx.x;
    g_fres[i] = f[i];
    g_fhat[i] = 0.0f;
    if (i < NSTAGE) g_m[i] = 0.0;
}

// ---------------- emb prep: e_sq + digit planes (scale 2^35) ----------------
__global__ void esq_kernel(const float* __restrict__ emb) {
    int gw = (blockIdx.x * blockDim.x + threadIdx.x) >> 5;
    int lane = threadIdx.x & 31;
    if (gw >= KCODE) return;
    float s = 0.0f;
    const float* row = emb + (size_t)gw * CDIM;
    #pragma unroll
    for (int c = lane; c < CDIM; c += 32) { float v = row[c]; s = __fmaf_rn(v, v, s); }
    #pragma unroll
    for (int o = 16; o; o >>= 1) s += __shfl_down_sync(0xffffffffu, s, o);
    if (lane == 0) g_esq[gw] = s;
}
__global__ void emb_split_kernel(const float* __restrict__ emb) {
    size_t i = (size_t)blockIdx.x * 256 + threadIdx.x;
    int E = __float2int_rn(emb[i] * 34359738368.0f);   // 2^35, |E| <= 2^22
    signed char d0, d1, d2;
    digit_split(E, d0, d1, d2);
    g_bd[0][i] = d0; g_bd[1][i] = d1; g_bd[2][i] = d2;
}

// ---------------- pool + t1 + rest digit planes (scale 2^20) ----------------
__global__ void pool_kernel(int pn) {
    int row = blockIdx.x;
    int b = row / pn, p = row - b * pn;
    int s = (p * NTOK) / pn;
    int e = ((p + 1) * NTOK + pn - 1) / pn;
    float w = (float)(1.0 / (double)(e - s));
    int c = threadIdx.x;
    float acc = 0.0f;
    for (int n = s; n < e; n++)
        acc = __fmaf_rn(w, g_fres[((size_t)b * NTOK + n) * CDIM + c], acc);

    int R = __float2int_rn(acc * 1048576.0f);          // 2^20
    R = max(-8323072, min(8323072, R));                // keep d2 in s8 (never triggers in practice)
    signed char d0, d1, d2;
    digit_split(R, d0, d1, d2);
    size_t off = (size_t)row * CDIM + c;
    g_ad[0][off] = d0; g_ad[1][off] = d1; g_ad[2][off] = d2;

    float sq = __fmul_rn(acc, acc);
    __shared__ float sm[8];
    int lane = threadIdx.x & 31, wid = threadIdx.x >> 5;
    #pragma unroll
    for (int o = 16; o; o >>= 1) sq += __shfl_down_sync(0xffffffffu, sq, o);
    if (lane == 0) sm[wid] = sq;
    __syncthreads();
    if (wid == 0) {
        float v = (lane < 8) ? sm[lane] : 0.0f;
        #pragma unroll
        for (int o = 4; o; o >>= 1) v += __shfl_down_sync(0xffffffffu, v, o);
        if (lane == 0) g_t1[row] = v;
    }
}

// ---------------- exact-int8 distance GEMM + fused argmin ----------------
// CTA tile 128 rows x 64 codes; K=256 in 8 chunks of 32 s8.
// 8 digit-pair IMMA passes grouped by weight s=i+j into 4 exact s32 groups.
// smem: per buf 27648B = A planes 3x(128x48) + B planes 3x(64x48); x2 bufs; +t1/esq.
#define SROW 48
#define APL  (128 * SROW)     // 6144
#define BPL  (64 * SROW)      // 3072
#define BUFB 27648
#define SHF_OFF (2 * BUFB)    // 55296: t1[128], esq[64]
#define DIST_SMEM (SHF_OFF + 768)

__global__ __launch_bounds__(256, 1) void dist_imma_kernel() {
    extern __shared__ char sm[];
    uint32_t sb = smem_u32(sm);
    float* shf = (float*)(sm + SHF_OFF);
    int t = threadIdx.x, lane = t & 31, wid = t >> 5;
    int wm = wid >> 1, wn = wid & 1;          // 4 x 2 warps
    int r0 = blockIdx.x * 128;
    int k0 = blockIdx.y * 64;

    if (t < 128) shf[t] = g_t1[r0 + t];
    if (t < 64)  shf[128 + t] = g_esq[k0 + t];

    int acc[4][2][4][4];                       // [s-1][mt][nt][reg]
    #pragma unroll
    for (int s = 0; s < 4; s++)
        #pragma unroll
        for (int mt = 0; mt < 2; mt++)
            #pragma unroll
            for (int nt = 0; nt < 4; nt++)
                #pragma unroll
                for (int j = 0; j < 4; j++) acc[s][mt][nt][j] = 0;

    auto load_chunk = [&](int cb, int buf) {
        uint32_t base = sb + buf * BUFB;
        #pragma unroll
        for (int p = 0; p < 3; p++) {          // A: 3 planes * 128 rows * 2 halves = 768
            int idx = t + 256 * p;
            int pl = idx >> 8, rem = idx & 255, rr = rem >> 1, h = rem & 1;
            uint32_t dst = base + pl * APL + rr * SROW + h * 16;
            const signed char* src = &g_ad[pl][(size_t)(r0 + rr) * CDIM + cb * 32 + h * 16];
            CP_ASYNC16(dst, src);
        }
        {                                      // B: 3 planes * 64 rows * 2 halves = 384
            int idx = t;
            int pl = idx >> 7, rem = idx & 127, rr = rem >> 1, h = rem & 1;
            uint32_t dst = base + 3 * APL + pl * BPL + rr * SROW + h * 16;
            const signed char* src = &g_bd[pl][(size_t)(k0 + rr) * CDIM + cb * 32 + h * 16];
            CP_ASYNC16(dst, src);
            if (t < 128) {
                idx = 256 + t;
                pl = idx >> 7; rem = idx & 127; rr = rem >> 1; h = rem & 1;
                dst = base + 3 * APL + pl * BPL + rr * SROW + h * 16;
                src = &g_bd[pl][(size_t)(k0 + rr) * CDIM + cb * 32 + h * 16];
                CP_ASYNC16(dst, src);
            }
        }
        CP_COMMIT();
    };

    load_chunk(0, 0);
    int g = lane >> 2, q = lane & 3;

    for (int cb = 0; cb < 8; cb++) {
        int buf = cb & 1;
        if (cb < 7) { load_chunk(cb + 1, buf ^ 1); CP_WAIT(1); }
        else        { CP_WAIT(0); }
        __syncthreads();

        const char* A = sm + buf * BUFB;
        const char* B = A + 3 * APL;

        uint32_t bf[3][4][2];
        #pragma unroll
        for (int pl = 0; pl < 3; pl++)
            #pragma unroll
            for (int nt = 0; nt < 4; nt++) {
                const char* pb = B + pl * BPL + (wn * 32 + nt * 8 + g) * SROW + 4 * q;
                bf[pl][nt][0] = *(const uint32_t*)pb;
                bf[pl][nt][1] = *(const uint32_t*)(pb + 16);
            }

        #pragma unroll
        for (int da = 2; da >= 0; da--) {
            uint32_t af[2][4];
            #pragma unroll
            for (int mt = 0; mt < 2; mt++) {
                const char* pa = A + da * APL + (wm * 32 + mt * 16 + g) * SROW + 4 * q;
                af[mt][0] = *(const uint32_t*)pa;
                af[mt][1] = *(const uint32_t*)(pa + 8 * SROW);
                af[mt][2] = *(const uint32_t*)(pa + 16);
                af[mt][3] = *(const uint32_t*)(pa + 8 * SROW + 16);
            }
            #pragma unroll
            for (int db = 2; db >= 0; db--) {
                int s = da + db;
                if (s == 0) continue;          // drop a0*b0 (2e-12)
                #pragma unroll
                for (int mt = 0; mt < 2; mt++)
                    #pragma unroll
                    for (int nt = 0; nt < 4; nt++)
                        imma(acc[s - 1][mt][nt], af[mt], bf[db][nt]);
            }
        }
        __syncthreads();
    }

    // ---- epilogue: exact dot fold, d = fl(tt - 2*dotf), argmin first-index ties ----
    float* sd = (float*)sm;                    // [128][2]
    int*   si = (int*)(sm + 1024);
    const float SCL = 0x1p-55f;

    #pragma unroll
    for (int mt = 0; mt < 2; mt++) {
        #pragma unroll
        for (int h = 0; h < 2; h++) {
            int rl = wm * 32 + mt * 16 + g + 8 * h;
            float t1v = shf[rl];
            float bd = INFINITY;
            int   bk = 0x7fffffff;
            #pragma unroll
            for (int nt = 0; nt < 4; nt++) {
                #pragma unroll
                for (int j = 0; j < 2; j++) {
                    int reg = 2 * h + j;
                    long long v = (long long)acc[3][mt][nt][reg];
                    v = (v << 8) + acc[2][mt][nt][reg];
                    v = (v << 8) + acc[1][mt][nt][reg];
                    v = (v << 8) + acc[0][mt][nt][reg];
                    v <<= 8;
                    float dotf = __ll2float_rn(v) * SCL;
                    int kl = wn * 32 + nt * 8 + 2 * q + j;
                    int k = k0 + kl;
                    float tt = __fadd_rn(t1v, shf[128 + kl]);
                    float d  = __fmaf_rn(-2.0f, dotf, tt);
                    if (d < bd || (d == bd && k < bk)) { bd = d; bk = k; }
                }
            }
            #pragma unroll
            for (int o = 1; o < 4; o <<= 1) {
                float od = __shfl_xor_sync(0xffffffffu, bd, o);
                int   ok = __shfl_xor_sync(0xffffffffu, bk, o);
                if (od < bd || (od == bd && ok < bk)) { bd = od; bk = ok; }
            }
            if (q == 0) { sd[rl * 2 + wn] = bd; si[rl * 2 + wn] = bk; }
        }
    }
    __syncthreads();
    if (t < 128) {
        float bd = sd[t * 2];     int bk = si[t * 2];
        float od = sd[t * 2 + 1]; int ok = si[t * 2 + 1];
        if (od < bd || (od == bd && ok < bk)) { bd = od; bk = ok; }
        g_pd[(size_t)(r0 + t) * 128 + blockIdx.y] = bd;
        g_pi[(size_t)(r0 + t) * 128 + blockIdx.y] = bk;
    }
}

// ---------------- reduce argmin across 128 k-blocks ----------------
__global__ void argmin_reduce_kernel() {
    int row = blockIdx.x * 8 + threadIdx.y;
    int l = threadIdx.x;
    size_t base = (size_t)row * 128;
    float bd = g_pd[base + l];
    int   bk = g_pi[base + l];
    #pragma unroll
    for (int p = 1; p < 4; p++) {
        float od = g_pd[base + l + 32 * p];
        int   ok = g_pi[base + l + 32 * p];
        if (od < bd || (od == bd && ok < bk)) { bd = od; bk = ok; }
    }
    #pragma unroll
    for (int o = 16; o; o >>= 1) {
        float od = __shfl_down_sync(0xffffffffu, bd, o);
        int   ok = __shfl_down_sync(0xffffffffu, bk, o);
        if (od < bd || (od == bd && ok < bk)) { bd = od; bk = ok; }
    }
    if (l == 0) g_idx[row] = bk;
}

// ---------------- gather + upsample + update + stats ----------------
__global__ void update_kernel(const float* __restrict__ f, const float* __restrict__ emb,
                              int pn, int stage) {
    int bn = blockIdx.x;
    int n = bn & 15, b = bn >> 4;
    int c = threadIdx.x;

    double scale = (double)pn / 16.0;
    double pos = ((double)n + 0.5) * scale - 0.5;
    if (pos < 0.0) pos = 0.0;
    int i0 = (int)floor(pos);
    if (i0 > pn - 1) i0 = pn - 1;
    int i1 = (i0 + 1 < pn) ? i0 + 1 : pn - 1;
    double frac = pos - (double)i0;

    int base = b * pn;
    float hv;
    if (i1 == i0) {
        float wc = (float)((double)((float)(1.0 - frac)) + frac);
        int k0 = g_idx[base + i0];
        hv = __fmul_rn(wc, emb[(size_t)k0 * CDIM + c]);
    } else {
        float w0 = (float)(1.0 - frac);
        float w1 = (float)frac;
        int k0 = g_idx[base + i0];
        int k1 = g_idx[base + i1];
        hv = __fadd_rn(__fmul_rn(w0, emb[(size_t)k0 * CDIM + c]),
                       __fmul_rn(w1, emb[(size_t)k1 * CDIM + c]));
    }

    size_t off = (size_t)bn * CDIM + c;
    float fh = __fadd_rn(g_fhat[off], hv);
    g_fhat[off] = fh;
    g_fres[off] = __fadd_rn(g_fres[off], -hv);

    float diff = __fadd_rn(fh, -f[off]);
    double v = (double)diff * (double)diff;

    __shared__ double sm[8];
    int lane = threadIdx.x & 31, wid = threadIdx.x >> 5;
    #pragma unroll
    for (int o = 16; o; o >>= 1) v += __shfl_down_sync(0xffffffffu, v, o);
    if (lane == 0) sm[wid] = v;
    __syncthreads();
    if (wid == 0) {
        double w = (lane < 8) ? sm[lane] : 0.0;
        #pragma unroll
        for (int o = 4; o; o >>= 1) w += __shfl_down_sync(0xffffffffu, w, o);
        if (lane == 0) atomicAdd(&g_m[stage], w);
    }
}

// ---------------- outputs ----------------
__global__ void out_main_kernel(const float* __restrict__ f, float* __restrict__ out) {
    size_t i = (size_t)blockIdx.x * 256 + threadIdx.x;
    out[i] = __fadd_rn(__fadd_rn(g_fhat[i], -f[i]), f[i]);
}
__global__ void out_scalar_kernel(float* __restrict__ out) {
    if (threadIdx.x == 0 && blockIdx.x == 0) {
        float c = 0.0f, q = 0.0f;
        for (int s = 0; s < NSTAGE; s++) {
            float m = (float)(g_m[s] * (1.0 / 2097152.0));
            c = __fadd_rn(c, __fmul_rn(0.25f, m));
            q = __fadd_rn(q, m);
        }
        out[BNC]     = __fdiv_rn(c, 16.0f);
        out[BNC + 1] = __fdiv_rn(q, 16.0f);
    }
}

// ---------------- launch ----------------
extern "C" void kernel_launch(void* const* d_in, const int* in_sizes, int n_in,
                              void* d_out, int out_size) {
    const float* f   = (const float*)d_in[0];
    const float* emb = (const float*)d_in[1];
    float* out = (float*)d_out;

    cudaFuncSetAttribute(dist_imma_kernel, cudaFuncAttributeMaxDynamicSharedMemorySize, DIST_SMEM);

    init_kernel<<<BNC / 256, 256>>>(f);
    esq_kernel<<<(KCODE * 32) / 256, 256>>>(emb);
    emb_split_kernel<<<(KCODE * CDIM) / 256, 256>>>(emb);

    for (int pn = 1; pn <= NTOK; pn++) {
        int rows = BATCH * pn;
        pool_kernel<<<rows, 256>>>(pn);
        dim3 dg(rows / 128, KCODE / 64);
        dist_imma_kernel<<<dg, 256, DIST_SMEM>>>();
        argmin_reduce_kernel<<<rows / 8, dim3(32, 8)>>>();
        update_kernel<<<BATCH * NTOK, 256>>>(f, emb, pn, pn - 1);
    }

    out_main_kernel<<<BNC / 256, 256>>>(f, out);
    out_scalar_kernel<<<1, 32>>>(out);
}

// round 7
// speedup vs baseline: 1.1260x; 1.1260x over previous
#include <cuda_runtime.h>
#include <math.h>
#include <cstdint>

#define BATCH 512
#define NTOK  16
#define CDIM  256
#define KCODE 8192
#define NSTAGE 16
#define BNC (BATCH*NTOK*CDIM)   // 2097152

// ---------------- device globals (scratch) ----------------
__device__ float  g_fres[BNC];
__device__ float  g_fhat[BNC];
__device__ __align__(16) signed char g_ad[3][BNC];        // rest digits d0,d1,d2 (scale 2^20)
__device__ __align__(16) signed char g_bd[3][KCODE*CDIM]; // emb  digits d0,d1,d2 (scale 2^35)
__device__ float  g_t1[BATCH*NTOK];
__device__ float  g_esq[KCODE];
__device__ int    g_idx[BATCH*NTOK];
__device__ float  g_pd[BATCH*NTOK*128];
__device__ int    g_pi[BATCH*NTOK*128];
__device__ double g_m[NSTAGE];

// ---------------- helpers ----------------
#define CP_ASYNC16(dst, src) \
    asm volatile("cp.async.cg.shared.global [%0], [%1], 16;" :: "r"(dst), "l"(src) : "memory")
#define CP_COMMIT() asm volatile("cp.async.commit_group;" ::: "memory")
#define CP_WAIT(n)  asm volatile("cp.async.wait_group %0;" :: "n"(n) : "memory")
#define LDMX4(r0, r1, r2, r3, addr) \
    asm volatile("ldmatrix.sync.aligned.m8n8.x4.shared.b16 {%0,%1,%2,%3}, [%4];" \
        : "=r"(r0), "=r"(r1), "=r"(r2), "=r"(r3) : "r"(addr))

__device__ __forceinline__ uint32_t smem_u32(const void* p) {
    uint32_t a;
    asm("{ .reg .u64 t; cvta.to.shared.u64 t, %1; cvt.u32.u64 %0, t; }" : "=r"(a) : "l"(p));
    return a;
}
__device__ __forceinline__ void imma(int* c, const uint32_t* a, const uint32_t* b) {
    asm volatile("mma.sync.aligned.m16n8k32.row.col.s32.s8.s8.s32 "
        "{%0,%1,%2,%3}, {%4,%5,%6,%7}, {%8,%9}, {%0,%1,%2,%3};"
        : "+r"(c[0]), "+r"(c[1]), "+r"(c[2]), "+r"(c[3])
        : "r"(a[0]), "r"(a[1]), "r"(a[2]), "r"(a[3]), "r"(b[0]), "r"(b[1]));
}
__device__ __forceinline__ void digit_split(int R, signed char& d0, signed char& d1, signed char& d2) {
    int x0 = (int)(signed char)(R & 0xFF); R = (R - x0) >> 8;
    int x1 = (int)(signed char)(R & 0xFF); R = (R - x1) >> 8;
    d0 = (signed char)x0; d1 = (signed char)x1; d2 = (signed char)R;
}

// ---------------- init ----------------
__global__ void init_kernel(const float* __restrict__ f) {
    size_t i = (size_t)blockIdx.x * 256 + threadIdx.x;
    g_fres[i] = f[i];
    g_fhat[i] = 0.0f;
    if (i < NSTAGE) g_m[i] = 0.0;
}

// ---------------- emb prep ----------------
__global__ void esq_kernel(const float* __restrict__ emb) {
    int gw = (blockIdx.x * blockDim.x + threadIdx.x) >> 5;
    int lane = threadIdx.x & 31;
    if (gw >= KCODE) return;
    float s = 0.0f;
    const float* row = emb + (size_t)gw * CDIM;
    #pragma unroll
    for (int c = lane; c < CDIM; c += 32) { float v = row[c]; s = __fmaf_rn(v, v, s); }
    #pragma unroll
    for (int o = 16; o; o >>= 1) s += __shfl_down_sync(0xffffffffu, s, o);
    if (lane == 0) g_esq[gw] = s;
}
__global__ void emb_split_kernel(const float* __restrict__ emb) {
    size_t i = (size_t)blockIdx.x * 256 + threadIdx.x;
    int E = __float2int_rn(emb[i] * 34359738368.0f);   // 2^35
    signed char d0, d1, d2;
    digit_split(E, d0, d1, d2);
    g_bd[0][i] = d0; g_bd[1][i] = d1; g_bd[2][i] = d2;
}

// ---------------- pool + t1 + rest digit planes (scale 2^20) ----------------
__global__ void pool_kernel(int pn) {
    int row = blockIdx.x;
    int b = row / pn, p = row - b * pn;
    int s = (p * NTOK) / pn;
    int e = ((p + 1) * NTOK + pn - 1) / pn;
    float w = (float)(1.0 / (double)(e - s));
    int c = threadIdx.x;
    float acc = 0.0f;
    for (int n = s; n < e; n++)
        acc = __fmaf_rn(w, g_fres[((size_t)b * NTOK + n) * CDIM + c], acc);

    int R = __float2int_rn(acc * 1048576.0f);          // 2^20
    R = max(-8323072, min(8323072, R));
    signed char d0, d1, d2;
    digit_split(R, d0, d1, d2);
    size_t off = (size_t)row * CDIM + c;
    g_ad[0][off] = d0; g_ad[1][off] = d1; g_ad[2][off] = d2;

    float sq = __fmul_rn(acc, acc);
    __shared__ float sm[8];
    int lane = threadIdx.x & 31, wid = threadIdx.x >> 5;
    #pragma unroll
    for (int o = 16; o; o >>= 1) sq += __shfl_down_sync(0xffffffffu, sq, o);
    if (lane == 0) sm[wid] = sq;
    __syncthreads();
    if (wid == 0) {
        float v = (lane < 8) ? sm[lane] : 0.0f;
        #pragma unroll
        for (int o = 4; o; o >>= 1) v += __shfl_down_sync(0xffffffffu, v, o);
        if (lane == 0) g_t1[row] = v;
    }
}

// ---------------- exact-int8 distance GEMM + fused argmin (v2) ----------------
// CTA 128 rows x 64 codes; 512 threads = 16 warps (8M x 2N), warp tile 16x32.
// 8 digit-pair IMMA passes -> 4 exact s32 groups; ldmatrix.x4 fragment loads.
#define SROW 48
#define APL  (128 * SROW)     // 6144
#define BPL  (64 * SROW)      // 3072
#define BUFB (3 * APL + 3 * BPL)   // 27648
#define SHF_OFF (2 * BUFB)         // 55296
#define DIST_SMEM (SHF_OFF + 768)  // 56064

__global__ __launch_bounds__(512, 1) void dist_imma_kernel() {
    extern __shared__ char sm[];
    uint32_t sb = smem_u32(sm);
    float* shf = (float*)(sm + SHF_OFF);
    int t = threadIdx.x, lane = t & 31, wid = t >> 5;
    int wm = wid >> 1, wn = wid & 1;          // 8 x 2 warps
    int r0 = blockIdx.x * 128;
    int k0 = blockIdx.y * 64;

    if (t < 128) shf[t] = g_t1[r0 + t];
    if (t < 64)  shf[128 + t] = g_esq[k0 + t];

    int acc[4][4][4];                          // [group s-1][nt][reg]
    #pragma unroll
    for (int s = 0; s < 4; s++)
        #pragma unroll
        for (int nt = 0; nt < 4; nt++)
            #pragma unroll
            for (int j = 0; j < 4; j++) acc[s][nt][j] = 0;

    auto load_chunk = [&](int cb, int buf) {
        uint32_t base = sb + buf * BUFB;
        #pragma unroll
        for (int p = 0; p < 3; p++) {
            int idx = t + 512 * p;             // 1152 transfers of 16B
            if (idx < 1152) {
                if (idx < 768) {               // A: 3 planes x 128 rows x 2 halves
                    int pl = idx >> 8, rem = idx & 255, row = rem >> 1, h = rem & 1;
                    CP_ASYNC16(base + pl * APL + row * SROW + h * 16,
                               &g_ad[pl][(size_t)(r0 + row) * CDIM + cb * 32 + h * 16]);
                } else {                       // B: 3 planes x 64 rows x 2 halves
                    int j = idx - 768;
                    int pl = j >> 7, rem = j & 127, row = rem >> 1, h = rem & 1;
                    CP_ASYNC16(base + 3 * APL + pl * BPL + row * SROW + h * 16,
                               &g_bd[pl][(size_t)(k0 + row) * CDIM + cb * 32 + h * 16]);
                }
            }
        }
        CP_COMMIT();
    };

    load_chunk(0, 0);
    int g = lane >> 2, q = lane & 3;
    int lm = lane >> 3, lr = lane & 7;         // ldmatrix: matrix id, row-in-matrix

    for (int cb = 0; cb < 8; cb++) {
        int buf = cb & 1;
        if (cb < 7) { load_chunk(cb + 1, buf ^ 1); CP_WAIT(1); }
        else        { CP_WAIT(0); }
        __syncthreads();

        uint32_t Abase = sb + buf * BUFB;
        uint32_t Bbase = Abase + 3 * APL;

        // B fragments: per plane, 2 x ldmatrix.x4 covering 4 n8 tiles
        // matrix m = lm: nblk = m>>1, h = m&1
        uint32_t bf[3][4][2];
        #pragma unroll
        for (int pl = 0; pl < 3; pl++) {
            #pragma unroll
            for (int pr = 0; pr < 2; pr++) {
                uint32_t addr = Bbase + pl * BPL
                    + (uint32_t)(wn * 32 + pr * 16 + (lm >> 1) * 8 + lr) * SROW
                    + (uint32_t)(lm & 1) * 16;
                LDMX4(bf[pl][2 * pr][0], bf[pl][2 * pr][1],
                      bf[pl][2 * pr + 1][0], bf[pl][2 * pr + 1][1], addr);
            }
        }

        // A passes: matrix m = lm: rblk = m&1, h = m>>1
        #pragma unroll
        for (int da = 2; da >= 0; da--) {
            uint32_t af[4];
            uint32_t addr = Abase + da * APL
                + (uint32_t)(wm * 16 + (lm & 1) * 8 + lr) * SROW
                + (uint32_t)(lm >> 1) * 16;
            LDMX4(af[0], af[1], af[2], af[3], addr);
            #pragma unroll
            for (int db = 2; db >= 0; db--) {
                int s = da + db;
                if (s == 0) continue;          // drop a0*b0 (~2e-12)
                #pragma unroll
                for (int nt = 0; nt < 4; nt++)
                    imma(acc[s - 1][nt], af, bf[db][nt]);
            }
        }
        __syncthreads();
    }

    // ---- epilogue: exact fold, d = fl(tt - 2*dotf), argmin first-index ties ----
    float* sd = (float*)sm;                    // [128][2]
    int*   si = (int*)(sm + 1024);
    const float SCL = 0x1p-55f;

    #pragma unroll
    for (int h = 0; h < 2; h++) {
        int rl = wm * 16 + g + 8 * h;
        float t1v = shf[rl];
        float bd = INFINITY;
        int   bk = 0x7fffffff;
        #pragma unroll
        for (int nt = 0; nt < 4; nt++) {
            #pragma unroll
            for (int j = 0; j < 2; j++) {
                int reg = 2 * h + j;
                long long v = (long long)acc[3][nt][reg];
                v = (v << 8) + acc[2][nt][reg];
                v = (v << 8) + acc[1][nt][reg];
                v = (v << 8) + acc[0][nt][reg];
                v <<= 8;
                float dotf = __ll2float_rn(v) * SCL;
                int kl = wn * 32 + nt * 8 + 2 * q + j;
                int k = k0 + kl;
                float tt = __fadd_rn(t1v, shf[128 + kl]);
                float d  = __fmaf_rn(-2.0f, dotf, tt);
                if (d < bd || (d == bd && k < bk)) { bd = d; bk = k; }
            }
        }
        #pragma unroll
        for (int o = 1; o < 4; o <<= 1) {
            float od = __shfl_xor_sync(0xffffffffu, bd, o);
            int   ok = __shfl_xor_sync(0xffffffffu, bk, o);
            if (od < bd || (od == bd && ok < bk)) { bd = od; bk = ok; }
        }
        if (q == 0) { sd[rl * 2 + wn] = bd; si[rl * 2 + wn] = bk; }
    }
    __syncthreads();
    if (t < 128) {
        float bd = sd[t * 2];     int bk = si[t * 2];
        float od = sd[t * 2 + 1]; int ok = si[t * 2 + 1];
        if (od < bd || (od == bd && ok < bk)) { bd = od; bk = ok; }
        g_pd[(size_t)(r0 + t) * 128 + blockIdx.y] = bd;
        g_pi[(size_t)(r0 + t) * 128 + blockIdx.y] = bk;
    }
}

// ---------------- reduce argmin across 128 k-blocks ----------------
__global__ void argmin_reduce_kernel() {
    int row = blockIdx.x * 8 + threadIdx.y;
    int l = threadIdx.x;
    size_t base = (size_t)row * 128;
    float bd = g_pd[base + l];
    int   bk = g_pi[base + l];
    #pragma unroll
    for (int p = 1; p < 4; p++) {
        float od = g_pd[base + l + 32 * p];
        int   ok = g_pi[base + l + 32 * p];
        if (od < bd || (od == bd && ok < bk)) { bd = od; bk = ok; }
    }
    #pragma unroll
    for (int o = 16; o; o >>= 1) {
        float od = __shfl_down_sync(0xffffffffu, bd, o);
        int   ok = __shfl_down_sync(0xffffffffu, bk, o);
        if (od < bd || (od == bd && ok < bk)) { bd = od; bk = ok; }
    }
    if (l == 0) g_idx[row] = bk;
}

// ---------------- gather + upsample + update + stats ----------------
__global__ void update_kernel(const float* __restrict__ f, const float* __restrict__ emb,
                              int pn, int stage) {
    int bn = blockIdx.x;
    int n = bn & 15, b = bn >> 4;
    int c = threadIdx.x;

    double scale = (double)pn / 16.0;
    double pos = ((double)n + 0.5) * scale - 0.5;
    if (pos < 0.0) pos = 0.0;
    int i0 = (int)floor(pos);
    if (i0 > pn - 1) i0 = pn - 1;
    int i1 = (i0 + 1 < pn) ? i0 + 1 : pn - 1;
    double frac = pos - (double)i0;

    int base = b * pn;
    float hv;
    if (i1 == i0) {
        float wc = (float)((double)((float)(1.0 - frac)) + frac);
        int k0 = g_idx[base + i0];
        hv = __fmul_rn(wc, emb[(size_t)k0 * CDIM + c]);
    } else {
        float w0 = (float)(1.0 - frac);
        float w1 = (float)frac;
        int k0 = g_idx[base + i0];
        int k1 = g_idx[base + i1];
        hv = __fadd_rn(__fmul_rn(w0, emb[(size_t)k0 * CDIM + c]),
                       __fmul_rn(w1, emb[(size_t)k1 * CDIM + c]));
    }

    size_t off = (size_t)bn * CDIM + c;
    float fh = __fadd_rn(g_fhat[off], hv);
    g_fhat[off] = fh;
    g_fres[off] = __fadd_rn(g_fres[off], -hv);

    float diff = __fadd_rn(fh, -f[off]);
    double v = (double)diff * (double)diff;

    __shared__ double sm[8];
    int lane = threadIdx.x & 31, wid = threadIdx.x >> 5;
    #pragma unroll
    for (int o = 16; o; o >>= 1) v += __shfl_down_sync(0xffffffffu, v, o);
    if (lane == 0) sm[wid] = v;
    __syncthreads();
    if (wid == 0) {
        double w = (lane < 8) ? sm[lane] : 0.0;
        #pragma unroll
        for (int o = 4; o; o >>= 1) w += __shfl_down_sync(0xffffffffu, w, o);
        if (lane == 0) atomicAdd(&g_m[stage], w);
    }
}

// ---------------- outputs ----------------
__global__ void out_main_kernel(const float* __restrict__ f, float* __restrict__ out) {
    size_t i = (size_t)blockIdx.x * 256 + threadIdx.x;
    out[i] = __fadd_rn(__fadd_rn(g_fhat[i], -f[i]), f[i]);
}
__global__ void out_scalar_kernel(float* __restrict__ out) {
    if (threadIdx.x == 0 && blockIdx.x == 0) {
        float c = 0.0f, q = 0.0f;
        for (int s = 0; s < NSTAGE; s++) {
            float m = (float)(g_m[s] * (1.0 / 2097152.0));
            c = __fadd_rn(c, __fmul_rn(0.25f, m));
            q = __fadd_rn(q, m);
        }
        out[BNC]     = __fdiv_rn(c, 16.0f);
        out[BNC + 1] = __fdiv_rn(q, 16.0f);
    }
}

// ---------------- launch ----------------
extern "C" void kernel_launch(void* const* d_in, const int* in_sizes, int n_in,
                              void* d_out, int out_size) {
    const float* f   = (const float*)d_in[0];
    const float* emb = (const float*)d_in[1];
    float* out = (float*)d_out;

    cudaFuncSetAttribute(dist_imma_kernel, cudaFuncAttributeMaxDynamicSharedMemorySize, DIST_SMEM);

    init_kernel<<<BNC / 256, 256>>>(f);
    esq_kernel<<<(KCODE * 32) / 256, 256>>>(emb);
    emb_split_kernel<<<(KCODE * CDIM) / 256, 256>>>(emb);

    for (int pn = 1; pn <= NTOK; pn++) {
        int rows = BATCH * pn;
        pool_kernel<<<rows, 256>>>(pn);
        dim3 dg(rows / 128, KCODE / 64);
        dist_imma_kernel<<<dg, 512, DIST_SMEM>>>();
        argmin_reduce_kernel<<<rows / 8, dim3(32, 8)>>>();
        update_kernel<<<BATCH * NTOK, 256>>>(f, emb, pn, pn - 1);
    }

    out_main_kernel<<<BNC / 256, 256>>>(f, out);
    out_scalar_kernel<<<1, 32>>>(out);
}

// round 9
// speedup vs baseline: 2.5133x; 2.2320x over previous
#include <cuda_runtime.h>
#include <math.h>
#include <cstdint>

#define BATCH 512
#define NTOK  16
#define CDIM  256
#define KCODE 8192
#define NSTAGE 16
#define BNC (BATCH*NTOK*CDIM)   // 2097152

// ---------------- device globals (scratch) ----------------
__device__ float  g_fres[BNC];
__device__ float  g_fhat[BNC];
__device__ float  g_rest[BATCH*NTOK*CDIM];
__device__ float  g_t1[BATCH*NTOK];
__device__ float  g_esq[KCODE];
__device__ int    g_idx[BATCH*NTOK];
__device__ float  g_pd[BATCH*NTOK*64];
__device__ int    g_pi[BATCH*NTOK*64];
__device__ double g_m[NSTAGE];

// ---------------- packed f32x2 helpers ----------------
__device__ __forceinline__ void ffma2(unsigned long long& acc, unsigned long long a, unsigned long long b) {
    asm("fma.rn.f32x2 %0, %1, %2, %0;" : "+l"(acc) : "l"(a), "l"(b));
}
__device__ __forceinline__ unsigned long long pack_dup(float v) {
    unsigned long long r;
    asm("mov.b64 %0, {%1, %1};" : "=l"(r) : "r"(__float_as_uint(v)));
    return r;
}
__device__ __forceinline__ void unpack2(unsigned long long p, float& lo, float& hi) {
    uint32_t a, b;
    asm("mov.b64 {%0, %1}, %2;" : "=r"(a), "=r"(b) : "l"(p));
    lo = __uint_as_float(a); hi = __uint_as_float(b);
}

// ---------------- init ----------------
__global__ void init_kernel(const float* __restrict__ f) {
    size_t i = (size_t)blockIdx.x * 256 + threadIdx.x;
    g_fres[i] = f[i];
    g_fhat[i] = 0.0f;
    if (i < NSTAGE) g_m[i] = 0.0;
}

// ---------------- e_sq ----------------
__global__ void esq_kernel(const float* __restrict__ emb) {
    int gw = (blockIdx.x * blockDim.x + threadIdx.x) >> 5;
    int lane = threadIdx.x & 31;
    if (gw >= KCODE) return;
    float s = 0.0f;
    const float* row = emb + (size_t)gw * CDIM;
    #pragma unroll
    for (int c = lane; c < CDIM; c += 32) { float v = row[c]; s = __fmaf_rn(v, v, s); }
    #pragma unroll
    for (int o = 16; o; o >>= 1) s += __shfl_down_sync(0xffffffffu, s, o);
    if (lane == 0) g_esq[gw] = s;
}

// ---------------- pool + t1 ----------------
__global__ void pool_kernel(int pn) {
    int row = blockIdx.x;
    int b = row / pn, p = row - b * pn;
    int s = (p * NTOK) / pn;
    int e = ((p + 1) * NTOK + pn - 1) / pn;
    float w = (float)(1.0 / (double)(e - s));
    int c = threadIdx.x;
    float acc = 0.0f;
    for (int n = s; n < e; n++)
        acc = __fmaf_rn(w, g_fres[((size_t)b * NTOK + n) * CDIM + c], acc);
    g_rest[(size_t)row * CDIM + c] = acc;

    float sq = __fmul_rn(acc, acc);
    __shared__ float sm[8];
    int lane = threadIdx.x & 31, wid = threadIdx.x >> 5;
    #pragma unroll
    for (int o = 16; o; o >>= 1) sq += __shfl_down_sync(0xffffffffu, sq, o);
    if (lane == 0) sm[wid] = sq;
    __syncthreads();
    if (wid == 0) {
        float v = (lane < 8) ? sm[lane] : 0.0f;
        #pragma unroll
        for (int o = 4; o; o >>= 1) v += __shfl_down_sync(0xffffffffu, v, o);
        if (lane == 0) g_t1[row] = v;
    }
}

// ---------------- FFMA2 distance GEMM + fused argmin ----------------
// Tile 128 rows x 128 codes; K in 8 chunks of 32. 256 threads, 8x8 microtile,
// accumulators as 32 packed f32x2 (pairs over adjacent codes). Bit-identical
// fp32 FMA chains to the round-1 kernel. Register-staged float4 prefetch.
__global__ __launch_bounds__(256, 2) void dist_kernel(const float* __restrict__ emb) {
    __shared__ __align__(16) float As[32][129];   // [c][m]
    __shared__ __align__(16) float Bs[32][130];   // [c][n] (even pad -> aligned pairs)
    int r0 = blockIdx.x * 128;
    int k0 = blockIdx.y * 128;
    int t  = threadIdx.x;
    int tx = t & 15, ty = t >> 4;

    unsigned long long acc[8][4];
    #pragma unroll
    for (int i = 0; i < 8; i++)
        #pragma unroll
        for (int j = 0; j < 4; j++) acc[i][j] = 0ull;

    float4 sa[4], sb[4];
    auto ldg_stage = [&](int cb) {
        #pragma unroll
        for (int p = 0; p < 4; p++) {
            int id = t + 256 * p;
            int m = id >> 3, c4 = id & 7;
            sa[p] = *(const float4*)(g_rest + (size_t)(r0 + m) * CDIM + cb * 32 + c4 * 4);
            sb[p] = *(const float4*)(emb    + (size_t)(k0 + m) * CDIM + cb * 32 + c4 * 4);
        }
    };
    auto sts_stage = [&]() {
        #pragma unroll
        for (int p = 0; p < 4; p++) {
            int id = t + 256 * p;
            int m = id >> 3, c4 = id & 7;
            As[c4 * 4 + 0][m] = sa[p].x; As[c4 * 4 + 1][m] = sa[p].y;
            As[c4 * 4 + 2][m] = sa[p].z; As[c4 * 4 + 3][m] = sa[p].w;
            Bs[c4 * 4 + 0][m] = sb[p].x; Bs[c4 * 4 + 1][m] = sb[p].y;
            Bs[c4 * 4 + 2][m] = sb[p].z; Bs[c4 * 4 + 3][m] = sb[p].w;
        }
    };

    ldg_stage(0);
    for (int cb = 0; cb < 8; cb++) {
        sts_stage();
        __syncthreads();
        if (cb < 7) ldg_stage(cb + 1);     // overlaps with compute below
        #pragma unroll
        for (int c = 0; c < 32; c++) {
            unsigned long long bp[4];
            #pragma unroll
            for (int j = 0; j < 4; j++)
                bp[j] = *(const unsigned long long*)&Bs[c][2 * tx + 32 * j];
            #pragma unroll
            for (int i = 0; i < 8; i++) {
                unsigned long long ap = pack_dup(As[c][ty + 16 * i]);
                #pragma unroll
                for (int j = 0; j < 4; j++)
                    ffma2(acc[i][j], ap, bp[j]);
            }
        }
        __syncthreads();
    }

    // ---- epilogue: d = fl(fl(t1+e_sq) - 2*dot); argmin, first-index ties ----
    #pragma unroll
    for (int i = 0; i < 8; i++) {
        int row = r0 + ty + 16 * i;
        float t1 = g_t1[row];
        float bd = INFINITY;
        int   bk = 0x7fffffff;
        #pragma unroll
        for (int j = 0; j < 4; j++) {
            float lo, hi;
            unpack2(acc[i][j], lo, hi);
            int k = k0 + 2 * tx + 32 * j;
            float tt0 = __fadd_rn(t1, g_esq[k]);
            float d0  = __fmaf_rn(-2.0f, lo, tt0);
            if (d0 < bd || (d0 == bd && k < bk)) { bd = d0; bk = k; }
            float tt1 = __fadd_rn(t1, g_esq[k + 1]);
            float d1  = __fmaf_rn(-2.0f, hi, tt1);
            if (d1 < bd || (d1 == bd && (k + 1) < bk)) { bd = d1; bk = k + 1; }
        }
        #pragma unroll
        for (int o = 8; o; o >>= 1) {
            float od = __shfl_down_sync(0xffffffffu, bd, o, 16);
            int   ok = __shfl_down_sync(0xffffffffu, bk, o, 16);
            if (od < bd || (od == bd && ok < bk)) { bd = od; bk = ok; }
        }
        if (tx == 0) {
            g_pd[(size_t)row * 64 + blockIdx.y] = bd;
            g_pi[(size_t)row * 64 + blockIdx.y] = bk;
        }
    }
}

// ---------------- reduce argmin across 64 k-blocks ----------------
__global__ void argmin_reduce_kernel() {
    int row = blockIdx.x * 8 + threadIdx.y;
    int l = threadIdx.x;
    size_t base = (size_t)row * 64;
    float bd = g_pd[base + l];      int bk = g_pi[base + l];
    float d2 = g_pd[base + l + 32]; int k2 = g_pi[base + l + 32];
    if (d2 < bd || (d2 == bd && k2 < bk)) { bd = d2; bk = k2; }
    #pragma unroll
    for (int o = 16; o; o >>= 1) {
        float od = __shfl_down_sync(0xffffffffu, bd, o);
        int   ok = __shfl_down_sync(0xffffffffu, bk, o);
        if (od < bd || (od == bd && ok < bk)) { bd = od; bk = ok; }
    }
    if (l == 0) g_idx[row] = bk;
}

// ---------------- gather + upsample + update + stats ----------------
__global__ void update_kernel(const float* __restrict__ f, const float* __restrict__ emb,
                              int pn, int stage) {
    int bn = blockIdx.x;
    int n = bn & 15, b = bn >> 4;
    int c = threadIdx.x;

    double scale = (double)pn / 16.0;
    double pos = ((double)n + 0.5) * scale - 0.5;
    if (pos < 0.0) pos = 0.0;
    int i0 = (int)floor(pos);
    if (i0 > pn - 1) i0 = pn - 1;
    int i1 = (i0 + 1 < pn) ? i0 + 1 : pn - 1;
    double frac = pos - (double)i0;

    int base = b * pn;
    float hv;
    if (i1 == i0) {
        float wc = (float)((double)((float)(1.0 - frac)) + frac);
        int k0 = g_idx[base + i0];
        hv = __fmul_rn(wc, emb[(size_t)k0 * CDIM + c]);
    } else {
        float w0 = (float)(1.0 - frac);
        float w1 = (float)frac;
        int k0 = g_idx[base + i0];
        int k1 = g_idx[base + i1];
        hv = __fadd_rn(__fmul_rn(w0, emb[(size_t)k0 * CDIM + c]),
                       __fmul_rn(w1, emb[(size_t)k1 * CDIM + c]));
    }

    size_t off = (size_t)bn * CDIM + c;
    float fh = __fadd_rn(g_fhat[off], hv);
    g_fhat[off] = fh;
    g_fres[off] = __fadd_rn(g_fres[off], -hv);

    float diff = __fadd_rn(fh, -f[off]);
    double v = (double)diff * (double)diff;

    __shared__ double sm[8];
    int lane = threadIdx.x & 31, wid = threadIdx.x >> 5;
    #pragma unroll
    for (int o = 16; o; o >>= 1) v += __shfl_down_sync(0xffffffffu, v, o);
    if (lane == 0) sm[wid] = v;
    __syncthreads();
    if (wid == 0) {
        double w = (lane < 8) ? sm[lane] : 0.0;
        #pragma unroll
        for (int o = 4; o; o >>= 1) w += __shfl_down_sync(0xffffffffu, w, o);
        if (lane == 0) atomicAdd(&g_m[stage], w);
    }
}

// ---------------- outputs ----------------
__global__ void out_main_kernel(const float* __restrict__ f, float* __restrict__ out) {
    size_t i = (size_t)blockIdx.x * 256 + threadIdx.x;
    out[i] = __fadd_rn(__fadd_rn(g_fhat[i], -f[i]), f[i]);
}
__global__ void out_scalar_kernel(float* __restrict__ out) {
    if (threadIdx.x == 0 && blockIdx.x == 0) {
        float c = 0.0f, q = 0.0f;
        for (int s = 0; s < NSTAGE; s++) {
            float m = (float)(g_m[s] * (1.0 / 2097152.0));
            c = __fadd_rn(c, __fmul_rn(0.25f, m));
            q = __fadd_rn(q, m);
        }
        out[BNC]     = __fdiv_rn(c, 16.0f);
        out[BNC + 1] = __fdiv_rn(q, 16.0f);
    }
}

// ---------------- launch ----------------
extern "C" void kernel_launch(void* const* d_in, const int* in_sizes, int n_in,
                              void* d_out, int out_size) {
    const float* f   = (const float*)d_in[0];
    const float* emb = (const float*)d_in[1];
    float* out = (float*)d_out;

    init_kernel<<<BNC / 256, 256>>>(f);
    esq_kernel<<<(KCODE * 32) / 256, 256>>>(emb);

    for (int pn = 1; pn <= NTOK; pn++) {
        int rows = BATCH * pn;
        pool_kernel<<<rows, 256>>>(pn);
        dim3 dg(rows / 128, KCODE / 128);
        dist_kernel<<<dg, 256>>>(emb);
        argmin_reduce_kernel<<<rows / 8, dim3(32, 8)>>>();
        update_kernel<<<BATCH * NTOK, 256>>>(f, emb, pn, pn - 1);
    }

    out_main_kernel<<<BNC / 256, 256>>>(f, out);
    out_scalar_kernel<<<1, 32>>>(out);
}